// round 16
// baseline (speedup 1.0000x reference)
#include <cuda_runtime.h>
#include <cuda_bf16.h>

// Problem constants
#define SEQ   4096
#define EMB   128
#define HID   128
#define G4    512          // 4*HID gate rows
#define NT    16

// Scratch (device globals; no allocation allowed)
__device__ int   g_tok[SEQ];
__device__ float g_pre[(SEQ + 1) * G4];   // +1 row so prefetch never branches
__device__ float g_hs[SEQ * HID];

typedef unsigned long long ull;

// ---------------------------------------------------------------------------
// fast math helpers
// ---------------------------------------------------------------------------
__device__ __forceinline__ float f_ex2(float x) {
    float y; asm("ex2.approx.f32 %0, %1;" : "=f"(y) : "f"(x)); return y;
}
__device__ __forceinline__ float f_rcp(float x) {
    float y; asm("rcp.approx.f32 %0, %1;" : "=f"(y) : "f"(x)); return y;
}
__device__ __forceinline__ float f_sigmoid(float x) {
    return f_rcp(1.0f + f_ex2(-1.4426950408889634f * x));
}
__device__ __forceinline__ float f_tanh(float x) {
    return 2.0f * f_sigmoid(2.0f * x) - 1.0f;
}

// packed f32x2 ops (sm_100+)
__device__ __forceinline__ ull ffma2(ull a, ull b, ull c) {
    ull d; asm("fma.rn.f32x2 %0, %1, %2, %3;" : "=l"(d) : "l"(a), "l"(b), "l"(c));
    return d;
}
__device__ __forceinline__ ull addf2(ull a, ull b) {
    ull d; asm("add.rn.f32x2 %0, %1, %2;" : "=l"(d) : "l"(a), "l"(b));
    return d;
}
__device__ __forceinline__ ull packf2(float lo, float hi) {
    ull r; asm("mov.b64 %0, {%1, %2};" : "=l"(r) : "f"(lo), "f"(hi)); return r;
}
__device__ __forceinline__ void unpackf2(float& lo, float& hi, ull v) {
    asm("mov.b64 {%0, %1}, %2;" : "=f"(lo), "=f"(hi) : "l"(v));
}
// one LDS.128 delivering two ready-to-use f32x2 operands
__device__ __forceinline__ void lds_v2b64(ull& a, ull& b, unsigned saddr) {
    asm volatile("ld.shared.v2.b64 {%0, %1}, [%2];" : "=l"(a), "=l"(b) : "r"(saddr));
}

// ---------------------------------------------------------------------------
// Kernel 0: normalize tokens to int32 (int64 delivered as 2x int32, or int32).
// ---------------------------------------------------------------------------
__global__ void tokenize_kernel(const int* __restrict__ xi) {
    __shared__ int is64;
    if (threadIdx.x == 0) {
        int nz = 0;
        #pragma unroll
        for (int i = 0; i < 64; ++i) nz += (xi[2 * i + 1] != 0);
        is64 = (nz == 0);
    }
    __syncthreads();
    int t = blockIdx.x * blockDim.x + threadIdx.x;
    if (t < SEQ) {
        if (is64) g_tok[t] = xi[2 * t];
        else      g_tok[t] = xi[t];
    }
}

// ---------------------------------------------------------------------------
// Kernel 1: pre[t][r] = b_ih[r] + b_hh[r] + sum_k emb[tok[t]][k] * w_ih[r][k]
// ---------------------------------------------------------------------------
__global__ void precompute_kernel(const float* __restrict__ emb,
                                  const float* __restrict__ w_ih,
                                  const float* __restrict__ b_ih,
                                  const float* __restrict__ b_hh,
                                  float* __restrict__ pre) {
    __shared__ float xe[16][128];
    const int t0 = blockIdx.x * 16;

    for (int i = threadIdx.x; i < 16 * 128; i += 256) {
        int ts = i >> 7, k = i & 127;
        long long tok = g_tok[t0 + ts];
        xe[ts][k] = emb[tok * (long long)EMB + k];
    }
    __syncthreads();

    #pragma unroll
    for (int rr = 0; rr < 2; ++rr) {
        const int r = threadIdx.x + rr * 256;
        const float bias = b_ih[r] + b_hh[r];
        float acc[16];
        #pragma unroll
        for (int ts = 0; ts < 16; ++ts) acc[ts] = bias;

        const float4* wrow = reinterpret_cast<const float4*>(w_ih + r * EMB);
        #pragma unroll 8
        for (int k4 = 0; k4 < EMB / 4; ++k4) {
            float4 w = wrow[k4];
            #pragma unroll
            for (int ts = 0; ts < 16; ++ts) {
                float4 h = reinterpret_cast<const float4*>(xe[ts])[k4];
                acc[ts] += w.x * h.x + w.y * h.y + w.z * h.z + w.w * h.w;
            }
        }
        #pragma unroll
        for (int ts = 0; ts < 16; ++ts)
            pre[(t0 + ts) * G4 + r] = acc[ts];
    }
}

// ---------------------------------------------------------------------------
// Kernel 2: recurrence. 1 block x 256 threads; thread r owns TWO gate rows:
//   rA = r, rB = r + 256. For r<128: (i, g); for r>=128: (f, o).
//   ONE shared h-load stream feeds both dots.
//   Per row: w[0:116] in 58 packed f32x2 register pairs (232 regs total),
//            w[116:128] in smem (stride-20 rows, phase-conflict-free).
//   4 accumulators total (8 regs) to stay under the 255-reg cap.
//   Epilogue: only f,o cross threads — packed float2 through zfo[].
// ---------------------------------------------------------------------------
#define NREG   116
#define NSH    (HID - NREG)       // 12
#define WS_STRIDE 20              // 12 + 8 pad; 20l mod 32 distinct per phase

__global__ void __launch_bounds__(256, 1)
lstm_kernel(const float* __restrict__ w_hh,
            const float* __restrict__ pre,
            float* __restrict__ hs) {
    extern __shared__ float smem[];
    float*  ws  = smem;                          // 512 * 20 floats (40960 B)
    float*  h_s = ws + G4 * WS_STRIDE;           // 128 floats (16B aligned)
    float2* zfo = reinterpret_cast<float2*>(h_s + HID);  // 128 float2

    const int r  = threadIdx.x;                  // 0..255
    const int rA = r;                            // i (r<128) / f gate rows
    const int rB = r + 256;                      // g (r<128) / o gate rows

    // --- pack register weights for both rows: [0:116] -> 58 pairs each ---
    ull wa[NREG / 2], wb[NREG / 2];
    {
        const float4* wrA = reinterpret_cast<const float4*>(w_hh + rA * HID);
        const float4* wrB = reinterpret_cast<const float4*>(w_hh + rB * HID);
        #pragma unroll
        for (int i = 0; i < NREG / 4; ++i) {
            float4 w = wrA[i];
            wa[2 * i]     = packf2(w.x, w.y);
            wa[2 * i + 1] = packf2(w.z, w.w);
            float4 v = wrB[i];
            wb[2 * i]     = packf2(v.x, v.y);
            wb[2 * i + 1] = packf2(v.z, v.w);
        }
    }
    // --- smem tails for all 512 rows: ws[row][k] = w_hh[row][116+k] ---
    for (int idx = r; idx < G4 * NSH; idx += 256) {
        int row = idx / NSH, k = idx - row * NSH;
        ws[row * WS_STRIDE + k] = w_hh[row * HID + NREG + k];
    }
    if (r < HID) h_s[r] = 0.0f;
    float c = 0.0f;

    const unsigned h_saddr = (unsigned)__cvta_generic_to_shared(h_s);
    const unsigned wsA     = (unsigned)__cvta_generic_to_shared(ws + rA * WS_STRIDE);
    const unsigned wsB     = (unsigned)__cvta_generic_to_shared(ws + rB * WS_STRIDE);
    const bool lo_half = (r < 128);              // (i,g) pair vs (f,o) pair

    float preA = pre[rA];
    float preB = pre[rB];
    __syncthreads();

    for (int s = 0; s < SEQ; ++s) {
        ull a0 = packf2(preA, 0.0f), a1 = 0;
        ull b0 = packf2(preB, 0.0f), b1 = 0;
        preA = pre[(s + 1) * G4 + rA];           // prefetch (row SEQ exists)
        preB = pre[(s + 1) * G4 + rB];

        // --- smem weight tail FIRST (h chunks 29..31), latency hides below ---
        #pragma unroll
        for (int i = 0; i < NSH / 4; ++i) {
            ull hp0, hp1, wa0, wa1, wb0, wb1;
            lds_v2b64(hp0, hp1, h_saddr + 16u * (NREG / 4 + i));
            lds_v2b64(wa0, wa1, wsA + 16u * i);
            lds_v2b64(wb0, wb1, wsB + 16u * i);
            a0 = ffma2(wa0, hp0, a0);  a1 = ffma2(wa1, hp1, a1);
            b0 = ffma2(wb0, hp0, b0);  b1 = ffma2(wb1, hp1, b1);
        }
        // --- register-resident 116: one h load feeds BOTH rows ---
        #pragma unroll
        for (int i = 0; i < NREG / 4; ++i) {
            ull hp0, hp1;
            lds_v2b64(hp0, hp1, h_saddr + 16u * i);
            a0 = ffma2(wa[2 * i],     hp0, a0);
            a1 = ffma2(wa[2 * i + 1], hp1, a1);
            b0 = ffma2(wb[2 * i],     hp0, b0);
            b1 = ffma2(wb[2 * i + 1], hp1, b1);
        }

        // packed reduction trees
        ull sa = addf2(a0, a1);
        ull sb = addf2(b0, b1);
        float xa0, xa1, xb0, xb1;
        unpackf2(xa0, xa1, sa);
        unpackf2(xb0, xb1, sb);
        float zA = xa0 + xa1;
        float zB = xb0 + xb1;

        float aA = f_sigmoid(zA);                          // i or f
        float aB = lo_half ? f_tanh(zB) : f_sigmoid(zB);   // g or o

        if (!lo_half) zfo[r - 128] = make_float2(aA, aB);  // {f, o}
        __syncthreads();

        if (lo_half) {
            float2 fo = zfo[r];                 // one LDS.64
            c = fo.x * c + aA * aB;             // f*c + i*g (both local!)
            float hv = fo.y * f_tanh(c);        // o * tanh(c)
            h_s[r] = hv;
            hs[s * HID + r] = hv;
        }
        __syncthreads();
    }
}

// ---------------------------------------------------------------------------
// Kernel 3: out[t][n] = b_fc[n] + sum_k hs[t][k] * w_fc[n][k]
// ---------------------------------------------------------------------------
__global__ void fc_kernel(const float* __restrict__ hs,
                          const float* __restrict__ w_fc,
                          const float* __restrict__ b_fc,
                          float* __restrict__ out) {
    __shared__ float sh[16][132];
    __shared__ float sw[16][132];
    const int t0 = blockIdx.x * 16;

    for (int i = threadIdx.x; i < 16 * 128; i += 256) {
        int rr = i >> 7, k = i & 127;
        sh[rr][k] = hs[(t0 + rr) * HID + k];
        sw[rr][k] = w_fc[rr * HID + k];
    }
    __syncthreads();

    const int ts = threadIdx.x >> 4;
    const int n  = threadIdx.x & 15;
    float acc = b_fc[n];
    #pragma unroll 8
    for (int k = 0; k < 128; ++k)
        acc += sh[ts][k] * sw[n][k];
    out[(t0 + ts) * NT + n] = acc;
}

// ---------------------------------------------------------------------------
extern "C" void kernel_launch(void* const* d_in, const int* in_sizes, int n_in,
                              void* d_out, int out_size) {
    const int*   x    = (const int*)d_in[0];
    const float* emb  = (const float*)d_in[1];
    const float* w_ih = (const float*)d_in[2];
    const float* w_hh = (const float*)d_in[3];
    const float* b_ih = (const float*)d_in[4];
    const float* b_hh = (const float*)d_in[5];
    const float* w_fc = (const float*)d_in[6];
    const float* b_fc = (const float*)d_in[7];
    float* out = (float*)d_out;

    float* pre; cudaGetSymbolAddress((void**)&pre, g_pre);
    float* hs;  cudaGetSymbolAddress((void**)&hs,  g_hs);

    const int lstm_smem = (G4 * WS_STRIDE + HID + 2 * HID) * (int)sizeof(float);
    cudaFuncSetAttribute(lstm_kernel,
                         cudaFuncAttributeMaxDynamicSharedMemorySize, lstm_smem);

    tokenize_kernel<<<SEQ / 256, 256>>>(x);
    precompute_kernel<<<SEQ / 16, 256>>>(emb, w_ih, b_ih, b_hh, pre);
    lstm_kernel<<<1, 256, lstm_smem>>>(w_hh, pre, hs);
    fc_kernel<<<SEQ / 16, 256>>>(hs, w_fc, b_fc, out);
}